// round 4
// baseline (speedup 1.0000x reference)
#include <cuda_runtime.h>
#include <cuda_bf16.h>
#include <cstdint>

#define MASK_PAD (-4294967295.0f)

// ---------------- byte offsets in dynamic SMEM ----------------
// padded row stride: 272 bytes (136 bf16) -> conflict-free ldmatrix
#define ROWB 272
#define SMB_BMH  0                         // M^T hi: 128 x 272
#define SMB_BML  (128 * ROWB)              // M^T lo          = 34816
#define SMB_W1H  (2 * 128 * ROWB)          // W1^T hi: 64x272 = 69632
#define SMB_W1L  (SMB_W1H + 64 * ROWB)     //                 = 87040
#define SMB_AH   (SMB_W1L + 64 * ROWB)     // K/H0 hi: 128x272= 104448
#define SMB_AL   (SMB_AH + 128 * ROWB)     //                 = 139264
#define SMB_C    (SMB_AL + 128 * ROWB)     // c vec 128 f     = 174080
#define SMB_B1   (SMB_C + 512)
#define SMB_WOUT (SMB_B1 + 256)
#define SMB_Q    (SMB_WOUT + 256)          // q / logit partials (128 f)
#define SMB_LOG  (SMB_Q + 512)             // 208 floats
#define SMB_RED  (SMB_LOG + 832)           // 32 floats
#define SMB_TOT  (SMB_RED + 128)           // 176704 bytes

__device__ float g_W0bc[128 * 128];   // W0b - W0c
__device__ float g_W0ac[128 * 128];   // W0a + W0c

__global__ void prep_kernel(const float* __restrict__ W0) {
    int idx = blockIdx.x * blockDim.x + threadIdx.x;
    if (idx < 128 * 128) {
        int i = idx >> 7, j = idx & 127;
        float wa = W0[i * 128 + j];
        float wb = W0[(128 + i) * 128 + j];
        float wc = W0[(256 + i) * 128 + j];
        g_W0bc[idx] = wb - wc;
        g_W0ac[idx] = wa + wc;
    }
}

__device__ __forceinline__ uint32_t smem_u32(const void* p) {
    uint32_t a;
    asm("{ .reg .u64 t; cvta.to.shared.u64 t, %1; cvt.u32.u64 %0, t; }" : "=r"(a) : "l"(p));
    return a;
}
__device__ __forceinline__ void ldsm_x4(uint32_t* r, uint32_t a) {
    asm volatile("ldmatrix.sync.aligned.m8n8.x4.shared.b16 {%0,%1,%2,%3}, [%4];"
                 : "=r"(r[0]), "=r"(r[1]), "=r"(r[2]), "=r"(r[3]) : "r"(a));
}
__device__ __forceinline__ void ldsm_x2(uint32_t* r, uint32_t a) {
    asm volatile("ldmatrix.sync.aligned.m8n8.x2.shared.b16 {%0,%1}, [%2];"
                 : "=r"(r[0]), "=r"(r[1]) : "r"(a));
}
__device__ __forceinline__ void mma16816(float* c, const uint32_t* a, const uint32_t* b) {
    asm volatile("mma.sync.aligned.m16n8k16.row.col.f32.bf16.bf16.f32 "
                 "{%0,%1,%2,%3}, {%4,%5,%6,%7}, {%8,%9}, {%0,%1,%2,%3};"
                 : "+f"(c[0]), "+f"(c[1]), "+f"(c[2]), "+f"(c[3])
                 : "r"(a[0]), "r"(a[1]), "r"(a[2]), "r"(a[3]), "r"(b[0]), "r"(b[1]));
}
// split fp32 -> (hi bf16, lo bf16)
__device__ __forceinline__ void split2(float x, unsigned short& h, unsigned short& l) {
    __nv_bfloat16 bh = __float2bfloat16_rn(x);
    float lo = x - __bfloat162float(bh);
    __nv_bfloat16 bl = __float2bfloat16_rn(lo);
    h = __bfloat16_as_ushort(bh);
    l = __bfloat16_as_ushort(bl);
}

__global__ void __launch_bounds__(256, 1)
din3_kernel(const float* __restrict__ query, const float* __restrict__ key,
            const float* __restrict__ val, const int* __restrict__ mask,
            const float* __restrict__ W0, const float* __restrict__ b0,
            const float* __restrict__ a0, const float* __restrict__ W1,
            const float* __restrict__ b1, const float* __restrict__ a1,
            const float* __restrict__ Wout, const float* __restrict__ bout,
            float* __restrict__ out) {
    extern __shared__ char smb[];
    const int tid = threadIdx.x;
    const int lane = tid & 31;
    const int wid = tid >> 5;
    const int b = blockIdx.x;
    const uint32_t sbase = smem_u32(smb);
    float* fC   = (float*)(smb + SMB_C);
    float* fB1  = (float*)(smb + SMB_B1);
    float* fWO  = (float*)(smb + SMB_WOUT);
    float* fQ   = (float*)(smb + SMB_Q);
    float* fLOG = (float*)(smb + SMB_LOG);
    float* fRED = (float*)(smb + SMB_RED);

    if (tid < 128) fQ[tid] = query[(size_t)b * 128 + tid];
    if (tid < 64) { fB1[tid] = b1[tid]; fWO[tid] = Wout[tid]; }
    __syncthreads();

    // ---- build M^T (rows h, cols k) bf16 hi/lo ----
    const float* W0d = W0 + 384 * 128;
    for (int p = 0; p < 32; p++) {                 // 8192 (h, k-pair)
        int idx = tid + p * 256;
        int kk = idx >> 7, h = idx & 127;
        int k0 = kk * 2;
        float m0 = g_W0bc[k0 * 128 + h] + fQ[k0] * W0d[k0 * 128 + h];
        float m1 = g_W0bc[(k0 + 1) * 128 + h] + fQ[k0 + 1] * W0d[(k0 + 1) * 128 + h];
        unsigned short h0, l0, h1, l1;
        split2(m0, h0, l0); split2(m1, h1, l1);
        uint32_t off = (uint32_t)(h * ROWB + k0 * 2);
        *(uint32_t*)(smb + SMB_BMH + off) = (uint32_t)h0 | ((uint32_t)h1 << 16);
        *(uint32_t*)(smb + SMB_BML + off) = (uint32_t)l0 | ((uint32_t)l1 << 16);
    }
    // ---- build W1^T (rows g, cols h) bf16 hi/lo ----
    for (int p = 0; p < 16; p++) {                 // 4096 (g, h-pair)
        int idx = tid + p * 256;
        int hh = idx >> 6, g = idx & 63;
        int h0i = hh * 2;
        unsigned short h0, l0, h1, l1;
        split2(W1[h0i * 64 + g], h0, l0);
        split2(W1[(h0i + 1) * 64 + g], h1, l1);
        uint32_t off = (uint32_t)(g * ROWB + h0i * 2);
        *(uint32_t*)(smb + SMB_W1H + off) = (uint32_t)h0 | ((uint32_t)h1 << 16);
        *(uint32_t*)(smb + SMB_W1L + off) = (uint32_t)l0 | ((uint32_t)l1 << 16);
    }
    // ---- c = q @ (W0a+W0c) + b0 ----
    if (tid < 128) {
        float s0 = 0.f, s1 = 0.f, s2 = 0.f, s3 = 0.f;
        for (int i = 0; i < 128; i += 4) {
            s0 += fQ[i + 0] * g_W0ac[(i + 0) * 128 + tid];
            s1 += fQ[i + 1] * g_W0ac[(i + 1) * 128 + tid];
            s2 += fQ[i + 2] * g_W0ac[(i + 2) * 128 + tid];
            s3 += fQ[i + 3] * g_W0ac[(i + 3) * 128 + tid];
        }
        fC[tid] = (s0 + s1) + (s2 + s3) + b0[tid];
    }
    __syncthreads();

    const int wm = wid & 3;          // row group (32 rows)
    const int wn = wid >> 2;         // col half
    // ldmatrix lane address components
    const uint32_t aRow = (uint32_t)((wm * 32 + (lane & 15)) * ROWB + ((lane >> 4) << 4));
    const uint32_t bRow1 = (uint32_t)((wn * 64 + (lane & 7)) * ROWB + (((lane >> 3) & 1) << 4));
    const uint32_t bRow2 = (uint32_t)((wn * 32 + (lane & 7)) * ROWB + (((lane >> 3) & 1) << 4));
    const int rbase = wm * 32 + (lane >> 2);

    for (int tile = 0; tile < 2; tile++) {
        const int base = tile * 128;

        // ---- load K tile, split -> A hi/lo ----
        #pragma unroll
        for (int p = 0; p < 16; p++) {
            int f4 = tid + p * 256;            // 4096 float4 slots
            int row = f4 >> 5;
            int c4 = (f4 & 31) << 2;
            int t = base + row;
            float4 v = make_float4(0.f, 0.f, 0.f, 0.f);
            if (t < 200) v = *(const float4*)&key[((size_t)b * 200 + t) * 128 + c4];
            unsigned short h0, l0, h1, l1, h2, l2, h3, l3;
            split2(v.x, h0, l0); split2(v.y, h1, l1);
            split2(v.z, h2, l2); split2(v.w, h3, l3);
            uint32_t off = (uint32_t)(row * ROWB + c4 * 2);
            *(unsigned long long*)(smb + SMB_AH + off) =
                (unsigned long long)h0 | ((unsigned long long)h1 << 16) |
                ((unsigned long long)h2 << 32) | ((unsigned long long)h3 << 48);
            *(unsigned long long*)(smb + SMB_AL + off) =
                (unsigned long long)l0 | ((unsigned long long)l1 << 16) |
                ((unsigned long long)l2 << 32) | ((unsigned long long)l3 << 48);
        }
        __syncthreads();

        // ---- GEMM1: acc[mi][ni] = (K @ M)[32x64 warp tile], 3-term split ----
        float acc[2][8][4];
        #pragma unroll
        for (int mi = 0; mi < 2; mi++)
            #pragma unroll
            for (int ni = 0; ni < 8; ni++)
                #pragma unroll
                for (int q = 0; q < 4; q++) acc[mi][ni][q] = 0.f;

        {
            const uint32_t Ab[3] = {sbase + SMB_AH, sbase + SMB_AH, sbase + SMB_AL};
            const uint32_t Bb[3] = {sbase + SMB_BMH, sbase + SMB_BML, sbase + SMB_BMH};
            #pragma unroll
            for (int term = 0; term < 3; term++) {
                #pragma unroll
                for (int k = 0; k < 8; k++) {
                    uint32_t af[2][4];
                    ldsm_x4(af[0], Ab[term] + aRow + k * 32);
                    ldsm_x4(af[1], Ab[term] + aRow + 16 * ROWB + k * 32);
                    uint32_t bf[8][2];
                    #pragma unroll
                    for (int ni = 0; ni < 8; ni++)
                        ldsm_x2(bf[ni], Bb[term] + bRow1 + ni * 8 * ROWB + k * 32);
                    #pragma unroll
                    for (int mi = 0; mi < 2; mi++)
                        #pragma unroll
                        for (int ni = 0; ni < 8; ni++)
                            mma16816(acc[mi][ni], af[mi], bf[ni]);
                }
            }
        }
        __syncthreads();   // all K reads done before H0 overwrites A region

        // ---- epilogue1: +c, PReLU(a0), split -> H0 hi/lo (A region) ----
        #pragma unroll
        for (int mi = 0; mi < 2; mi++)
            #pragma unroll
            for (int ni = 0; ni < 8; ni++)
                #pragma unroll
                for (int rr = 0; rr < 2; rr++) {
                    const int row = rbase + mi * 16 + rr * 8;
                    const int t = base + row;
                    const int col = wn * 64 + ni * 8 + (lane & 3) * 2;
                    float x0 = acc[mi][ni][rr * 2 + 0] + fC[col];
                    float x1 = acc[mi][ni][rr * 2 + 1] + fC[col + 1];
                    if (x0 < 0.f) x0 *= (t < 200 ? __ldg(&a0[t * 128 + col]) : 0.25f);
                    if (x1 < 0.f) x1 *= (t < 200 ? __ldg(&a0[t * 128 + col + 1]) : 0.25f);
                    unsigned short h0, l0, h1, l1;
                    split2(x0, h0, l0); split2(x1, h1, l1);
                    uint32_t off = (uint32_t)(row * ROWB + col * 2);
                    *(uint32_t*)(smb + SMB_AH + off) = (uint32_t)h0 | ((uint32_t)h1 << 16);
                    *(uint32_t*)(smb + SMB_AL + off) = (uint32_t)l0 | ((uint32_t)l1 << 16);
                }
        __syncthreads();

        // ---- GEMM2: acc2[mi][ni] = (H0 @ W1)[32x32 warp tile] ----
        float acc2[2][4][4];
        #pragma unroll
        for (int mi = 0; mi < 2; mi++)
            #pragma unroll
            for (int ni = 0; ni < 4; ni++)
                #pragma unroll
                for (int q = 0; q < 4; q++) acc2[mi][ni][q] = 0.f;
        {
            const uint32_t Ab[3] = {sbase + SMB_AH, sbase + SMB_AH, sbase + SMB_AL};
            const uint32_t Bb[3] = {sbase + SMB_W1H, sbase + SMB_W1L, sbase + SMB_W1H};
            #pragma unroll
            for (int term = 0; term < 3; term++) {
                #pragma unroll
                for (int k = 0; k < 8; k++) {
                    uint32_t af[2][4];
                    ldsm_x4(af[0], Ab[term] + aRow + k * 32);
                    ldsm_x4(af[1], Ab[term] + aRow + 16 * ROWB + k * 32);
                    uint32_t bf[4][2];
                    #pragma unroll
                    for (int ni = 0; ni < 4; ni++)
                        ldsm_x2(bf[ni], Bb[term] + bRow2 + ni * 8 * ROWB + k * 32);
                    #pragma unroll
                    for (int mi = 0; mi < 2; mi++)
                        #pragma unroll
                        for (int ni = 0; ni < 4; ni++)
                            mma16816(acc2[mi][ni], af[mi], bf[ni]);
                }
            }
        }

        // ---- epilogue2: +b1, PReLU(a1), dot Wout, reduce -> logits ----
        {
            float racc[4] = {0.f, 0.f, 0.f, 0.f};
            #pragma unroll
            for (int mi = 0; mi < 2; mi++)
                #pragma unroll
                for (int ni = 0; ni < 4; ni++)
                    #pragma unroll
                    for (int rr = 0; rr < 2; rr++) {
                        const int row = rbase + mi * 16 + rr * 8;
                        const int t = base + row;
                        const int g = wn * 32 + ni * 8 + (lane & 3) * 2;
                        float x0 = acc2[mi][ni][rr * 2 + 0] + fB1[g];
                        float x1 = acc2[mi][ni][rr * 2 + 1] + fB1[g + 1];
                        if (x0 < 0.f) x0 *= (t < 200 ? __ldg(&a1[t * 64 + g]) : 0.25f);
                        if (x1 < 0.f) x1 *= (t < 200 ? __ldg(&a1[t * 64 + g + 1]) : 0.25f);
                        racc[mi * 2 + rr] += x0 * fWO[g] + x1 * fWO[g + 1];
                    }
            #pragma unroll
            for (int i = 0; i < 4; i++) {
                racc[i] += __shfl_xor_sync(0xffffffffu, racc[i], 1);
                racc[i] += __shfl_xor_sync(0xffffffffu, racc[i], 2);
            }
            if (wn == 0 && (lane & 3) == 0) {
                #pragma unroll
                for (int i = 0; i < 4; i++)
                    fQ[rbase + (i >> 1) * 16 + (i & 1) * 8] = racc[i];
            }
            __syncthreads();
            if (wn == 1 && (lane & 3) == 0) {
                #pragma unroll
                for (int i = 0; i < 4; i++) {
                    const int row = rbase + (i >> 1) * 16 + (i & 1) * 8;
                    const int t = base + row;
                    if (t < 200) {
                        float lg = fQ[row] + racc[i] + bout[0];
                        if (mask[(size_t)b * 200 + t] == 0) lg = MASK_PAD;
                        fLOG[t] = lg;
                    }
                }
            }
            __syncthreads();
        }
    }

    // ---- softmax over 200 logits ----
    float v = (tid < 200) ? fLOG[tid] : -3.4e38f;
    float m = v;
    #pragma unroll
    for (int o = 16; o > 0; o >>= 1)
        m = fmaxf(m, __shfl_xor_sync(0xffffffffu, m, o));
    if (lane == 0) fRED[wid] = m;
    __syncthreads();
    float mx = fRED[0];
    #pragma unroll
    for (int i = 1; i < 8; i++) mx = fmaxf(mx, fRED[i]);
    float e = (tid < 200) ? expf(v - mx) : 0.f;
    float s = e;
    #pragma unroll
    for (int o = 16; o > 0; o >>= 1)
        s += __shfl_xor_sync(0xffffffffu, s, o);
    __syncthreads();
    if (lane == 0) fRED[wid] = s;
    __syncthreads();
    float tot = 0.f;
    #pragma unroll
    for (int i = 0; i < 8; i++) tot += fRED[i];
    if (tid < 200) fLOG[tid] = e / tot;
    __syncthreads();

    // ---- out[b,:] = attn @ V ----
    float* scr = (float*)(smb + SMB_AH);
    const int half = tid >> 7;
    const int dch = tid & 127;
    const float* vb = val + ((size_t)b * 200 + half * 100) * 128 + dch;
    const float* at = &fLOG[half * 100];
    float s0 = 0.f, s1 = 0.f, s2 = 0.f, s3 = 0.f;
    for (int t = 0; t < 100; t += 4) {
        s0 += at[t + 0] * vb[(size_t)(t + 0) * 128];
        s1 += at[t + 1] * vb[(size_t)(t + 1) * 128];
        s2 += at[t + 2] * vb[(size_t)(t + 2) * 128];
        s3 += at[t + 3] * vb[(size_t)(t + 3) * 128];
    }
    scr[tid] = (s0 + s1) + (s2 + s3);
    __syncthreads();
    if (tid < 128)
        out[(size_t)b * 128 + tid] = scr[tid] + scr[128 + tid];
}

extern "C" void kernel_launch(void* const* d_in, const int* in_sizes, int n_in,
                              void* d_out, int out_size) {
    (void)in_sizes; (void)n_in; (void)out_size;
    const float* query = (const float*)d_in[0];
    const float* key   = (const float*)d_in[1];
    const float* val   = (const float*)d_in[2];
    const int*   mask  = (const int*)d_in[3];
    const float* W0    = (const float*)d_in[4];
    const float* b0    = (const float*)d_in[5];
    const float* a0    = (const float*)d_in[6];
    const float* W1    = (const float*)d_in[7];
    const float* b1    = (const float*)d_in[8];
    const float* a1    = (const float*)d_in[9];
    const float* Wout  = (const float*)d_in[10];
    const float* bout  = (const float*)d_in[11];
    float* out = (float*)d_out;

    cudaFuncSetAttribute(din3_kernel, cudaFuncAttributeMaxDynamicSharedMemorySize,
                         SMB_TOT);
    prep_kernel<<<64, 256>>>(W0);
    din3_kernel<<<2048, 256, SMB_TOT>>>(query, key, val, mask, W0, b0, a0,
                                        W1, b1, a1, Wout, bout, out);
}

// round 5
// speedup vs baseline: 1.2349x; 1.2349x over previous
#include <cuda_runtime.h>
#include <cuda_bf16.h>
#include <cstdint>

#define MASK_PAD (-4294967295.0f)

// ---------------- byte offsets in dynamic SMEM ----------------
// padded row stride: 272 bytes (136 bf16) -> conflict-free ldmatrix
#define ROWB 272
#define SMB_BMH  0                         // M^T hi: 128 x 272
#define SMB_BML  (128 * ROWB)              // M^T lo          = 34816
#define SMB_W1H  (2 * 128 * ROWB)          // W1^T hi: 64x272 = 69632
#define SMB_W1L  (SMB_W1H + 64 * ROWB)     //                 = 87040
#define SMB_AH   (SMB_W1L + 64 * ROWB)     // K/H0 hi: 128x272= 104448
#define SMB_AL   (SMB_AH + 128 * ROWB)     //                 = 139264
#define SMB_C    (SMB_AL + 128 * ROWB)     // c vec 128 f     = 174080
#define SMB_B1   (SMB_C + 512)
#define SMB_WOUT (SMB_B1 + 256)
#define SMB_Q    (SMB_WOUT + 256)          // q / logit partials (128 f)
#define SMB_LOG  (SMB_Q + 512)             // 208 floats
#define SMB_RED  (SMB_LOG + 832)           // 64 floats
#define SMB_TOT  (SMB_RED + 256)           // ~176832 bytes

#define NTHR 512

__device__ float g_W0bc[128 * 128];   // W0b - W0c
__device__ float g_W0ac[128 * 128];   // W0a + W0c

__global__ void prep_kernel(const float* __restrict__ W0) {
    int idx = blockIdx.x * blockDim.x + threadIdx.x;
    if (idx < 128 * 128) {
        int i = idx >> 7, j = idx & 127;
        float wa = W0[i * 128 + j];
        float wb = W0[(128 + i) * 128 + j];
        float wc = W0[(256 + i) * 128 + j];
        g_W0bc[idx] = wb - wc;
        g_W0ac[idx] = wa + wc;
    }
}

__device__ __forceinline__ uint32_t smem_u32(const void* p) {
    uint32_t a;
    asm("{ .reg .u64 t; cvta.to.shared.u64 t, %1; cvt.u32.u64 %0, t; }" : "=r"(a) : "l"(p));
    return a;
}
__device__ __forceinline__ void ldsm_x4(uint32_t* r, uint32_t a) {
    asm volatile("ldmatrix.sync.aligned.m8n8.x4.shared.b16 {%0,%1,%2,%3}, [%4];"
                 : "=r"(r[0]), "=r"(r[1]), "=r"(r[2]), "=r"(r[3]) : "r"(a));
}
__device__ __forceinline__ void ldsm_x2(uint32_t* r, uint32_t a) {
    asm volatile("ldmatrix.sync.aligned.m8n8.x2.shared.b16 {%0,%1}, [%2];"
                 : "=r"(r[0]), "=r"(r[1]) : "r"(a));
}
__device__ __forceinline__ void mma16816(float* c, const uint32_t* a, const uint32_t* b) {
    asm volatile("mma.sync.aligned.m16n8k16.row.col.f32.bf16.bf16.f32 "
                 "{%0,%1,%2,%3}, {%4,%5,%6,%7}, {%8,%9}, {%0,%1,%2,%3};"
                 : "+f"(c[0]), "+f"(c[1]), "+f"(c[2]), "+f"(c[3])
                 : "r"(a[0]), "r"(a[1]), "r"(a[2]), "r"(a[3]), "r"(b[0]), "r"(b[1]));
}
// split fp32 -> (hi bf16, lo bf16)
__device__ __forceinline__ void split2(float x, unsigned short& h, unsigned short& l) {
    __nv_bfloat16 bh = __float2bfloat16_rn(x);
    float lo = x - __bfloat162float(bh);
    __nv_bfloat16 bl = __float2bfloat16_rn(lo);
    h = __bfloat16_as_ushort(bh);
    l = __bfloat16_as_ushort(bl);
}

__global__ void __launch_bounds__(NTHR, 1)
din4_kernel(const float* __restrict__ query, const float* __restrict__ key,
            const float* __restrict__ val, const int* __restrict__ mask,
            const float* __restrict__ W0, const float* __restrict__ b0,
            const float* __restrict__ a0, const float* __restrict__ W1,
            const float* __restrict__ b1, const float* __restrict__ a1,
            const float* __restrict__ Wout, const float* __restrict__ bout,
            float* __restrict__ out) {
    extern __shared__ char smb[];
    const int tid = threadIdx.x;
    const int lane = tid & 31;
    const int wid = tid >> 5;           // 0..15
    const int b = blockIdx.x;
    const uint32_t sbase = smem_u32(smb);
    float* fC   = (float*)(smb + SMB_C);
    float* fB1  = (float*)(smb + SMB_B1);
    float* fWO  = (float*)(smb + SMB_WOUT);
    float* fQ   = (float*)(smb + SMB_Q);
    float* fLOG = (float*)(smb + SMB_LOG);
    float* fRED = (float*)(smb + SMB_RED);

    if (tid < 128) fQ[tid] = query[(size_t)b * 128 + tid];
    if (tid < 64) { fB1[tid] = b1[tid]; fWO[tid] = Wout[tid]; }
    __syncthreads();

    // ---- build M^T (rows h, cols k) bf16 hi/lo ----
    const float* W0d = W0 + 384 * 128;
    #pragma unroll
    for (int p = 0; p < 16; p++) {                 // 8192 (h, k-pair)
        int idx = tid + p * NTHR;
        int kk = idx >> 7, h = idx & 127;
        int k0 = kk * 2;
        float m0 = g_W0bc[k0 * 128 + h] + fQ[k0] * W0d[k0 * 128 + h];
        float m1 = g_W0bc[(k0 + 1) * 128 + h] + fQ[k0 + 1] * W0d[(k0 + 1) * 128 + h];
        unsigned short h0, l0, h1, l1;
        split2(m0, h0, l0); split2(m1, h1, l1);
        uint32_t off = (uint32_t)(h * ROWB + k0 * 2);
        *(uint32_t*)(smb + SMB_BMH + off) = (uint32_t)h0 | ((uint32_t)h1 << 16);
        *(uint32_t*)(smb + SMB_BML + off) = (uint32_t)l0 | ((uint32_t)l1 << 16);
    }
    // ---- build W1^T (rows g, cols h) bf16 hi/lo ----
    #pragma unroll
    for (int p = 0; p < 8; p++) {                  // 4096 (g, h-pair)
        int idx = tid + p * NTHR;
        int hh = idx >> 6, g = idx & 63;
        int h0i = hh * 2;
        unsigned short h0, l0, h1, l1;
        split2(W1[h0i * 64 + g], h0, l0);
        split2(W1[(h0i + 1) * 64 + g], h1, l1);
        uint32_t off = (uint32_t)(g * ROWB + h0i * 2);
        *(uint32_t*)(smb + SMB_W1H + off) = (uint32_t)h0 | ((uint32_t)h1 << 16);
        *(uint32_t*)(smb + SMB_W1L + off) = (uint32_t)l0 | ((uint32_t)l1 << 16);
    }
    // ---- c = q @ (W0a+W0c) + b0 ----
    if (tid < 128) {
        float s0 = 0.f, s1 = 0.f, s2 = 0.f, s3 = 0.f;
        for (int i = 0; i < 128; i += 4) {
            s0 += fQ[i + 0] * g_W0ac[(i + 0) * 128 + tid];
            s1 += fQ[i + 1] * g_W0ac[(i + 1) * 128 + tid];
            s2 += fQ[i + 2] * g_W0ac[(i + 2) * 128 + tid];
            s3 += fQ[i + 3] * g_W0ac[(i + 3) * 128 + tid];
        }
        fC[tid] = (s0 + s1) + (s2 + s3) + b0[tid];
    }
    __syncthreads();

    const int wm = wid & 7;          // row group (16 rows)
    const int wn = wid >> 3;         // col half
    const uint32_t aRow = (uint32_t)((wm * 16 + (lane & 15)) * ROWB + ((lane >> 4) << 4));
    const uint32_t bRow1 = (uint32_t)((wn * 64 + (lane & 7)) * ROWB + (((lane >> 3) & 1) << 4));
    const uint32_t bRow2 = (uint32_t)((wn * 32 + (lane & 7)) * ROWB + (((lane >> 3) & 1) << 4));
    const int rbase = wm * 16 + (lane >> 2);

    for (int tile = 0; tile < 2; tile++) {
        const int base = tile * 128;

        // ---- load K tile, split -> A hi/lo ----
        #pragma unroll
        for (int p = 0; p < 8; p++) {
            int f4 = tid + p * NTHR;           // 4096 float4 slots
            int row = f4 >> 5;
            int c4 = (f4 & 31) << 2;
            int t = base + row;
            float4 v = make_float4(0.f, 0.f, 0.f, 0.f);
            if (t < 200) v = *(const float4*)&key[((size_t)b * 200 + t) * 128 + c4];
            unsigned short h0, l0, h1, l1, h2, l2, h3, l3;
            split2(v.x, h0, l0); split2(v.y, h1, l1);
            split2(v.z, h2, l2); split2(v.w, h3, l3);
            uint32_t off = (uint32_t)(row * ROWB + c4 * 2);
            *(unsigned long long*)(smb + SMB_AH + off) =
                (unsigned long long)h0 | ((unsigned long long)h1 << 16) |
                ((unsigned long long)h2 << 32) | ((unsigned long long)h3 << 48);
            *(unsigned long long*)(smb + SMB_AL + off) =
                (unsigned long long)l0 | ((unsigned long long)l1 << 16) |
                ((unsigned long long)l2 << 32) | ((unsigned long long)l3 << 48);
        }
        __syncthreads();

        // ---- GEMM1: 16x64 warp tile, 3-term bf16 split ----
        float acc[8][4];
        #pragma unroll
        for (int ni = 0; ni < 8; ni++)
            #pragma unroll
            for (int q = 0; q < 4; q++) acc[ni][q] = 0.f;
        {
            const uint32_t Ab[3] = {sbase + SMB_AH, sbase + SMB_AH, sbase + SMB_AL};
            const uint32_t Bb[3] = {sbase + SMB_BMH, sbase + SMB_BML, sbase + SMB_BMH};
            #pragma unroll
            for (int term = 0; term < 3; term++) {
                #pragma unroll
                for (int k = 0; k < 8; k++) {
                    uint32_t af[4];
                    ldsm_x4(af, Ab[term] + aRow + k * 32);
                    uint32_t bf[8][2];
                    #pragma unroll
                    for (int ni = 0; ni < 8; ni++)
                        ldsm_x2(bf[ni], Bb[term] + bRow1 + ni * 8 * ROWB + k * 32);
                    #pragma unroll
                    for (int ni = 0; ni < 8; ni++)
                        mma16816(acc[ni], af, bf[ni]);
                }
            }
        }
        __syncthreads();   // all K reads done before H0 overwrites A region

        // ---- epilogue1: +c, PReLU(a0), split -> H0 hi/lo (A region) ----
        #pragma unroll
        for (int ni = 0; ni < 8; ni++)
            #pragma unroll
            for (int rr = 0; rr < 2; rr++) {
                const int row = rbase + rr * 8;
                const int t = base + row;
                const int col = wn * 64 + ni * 8 + (lane & 3) * 2;
                float x0 = acc[ni][rr * 2 + 0] + fC[col];
                float x1 = acc[ni][rr * 2 + 1] + fC[col + 1];
                if (x0 < 0.f) x0 *= (t < 200 ? __ldg(&a0[t * 128 + col]) : 0.25f);
                if (x1 < 0.f) x1 *= (t < 200 ? __ldg(&a0[t * 128 + col + 1]) : 0.25f);
                unsigned short h0, l0, h1, l1;
                split2(x0, h0, l0); split2(x1, h1, l1);
                uint32_t off = (uint32_t)(row * ROWB + col * 2);
                *(uint32_t*)(smb + SMB_AH + off) = (uint32_t)h0 | ((uint32_t)h1 << 16);
                *(uint32_t*)(smb + SMB_AL + off) = (uint32_t)l0 | ((uint32_t)l1 << 16);
            }
        __syncthreads();

        // ---- GEMM2: 16x32 warp tile ----
        float acc2[4][4];
        #pragma unroll
        for (int ni = 0; ni < 4; ni++)
            #pragma unroll
            for (int q = 0; q < 4; q++) acc2[ni][q] = 0.f;
        {
            const uint32_t Ab[3] = {sbase + SMB_AH, sbase + SMB_AH, sbase + SMB_AL};
            const uint32_t Bb[3] = {sbase + SMB_W1H, sbase + SMB_W1L, sbase + SMB_W1H};
            #pragma unroll
            for (int term = 0; term < 3; term++) {
                #pragma unroll
                for (int k = 0; k < 8; k++) {
                    uint32_t af[4];
                    ldsm_x4(af, Ab[term] + aRow + k * 32);
                    uint32_t bf[4][2];
                    #pragma unroll
                    for (int ni = 0; ni < 4; ni++)
                        ldsm_x2(bf[ni], Bb[term] + bRow2 + ni * 8 * ROWB + k * 32);
                    #pragma unroll
                    for (int ni = 0; ni < 4; ni++)
                        mma16816(acc2[ni], af, bf[ni]);
                }
            }
        }

        // ---- epilogue2: +b1, PReLU(a1), dot Wout, reduce -> logits ----
        {
            float racc[2] = {0.f, 0.f};
            #pragma unroll
            for (int ni = 0; ni < 4; ni++)
                #pragma unroll
                for (int rr = 0; rr < 2; rr++) {
                    const int row = rbase + rr * 8;
                    const int t = base + row;
                    const int g = wn * 32 + ni * 8 + (lane & 3) * 2;
                    float x0 = acc2[ni][rr * 2 + 0] + fB1[g];
                    float x1 = acc2[ni][rr * 2 + 1] + fB1[g + 1];
                    if (x0 < 0.f) x0 *= (t < 200 ? __ldg(&a1[t * 64 + g]) : 0.25f);
                    if (x1 < 0.f) x1 *= (t < 200 ? __ldg(&a1[t * 64 + g + 1]) : 0.25f);
                    racc[rr] += x0 * fWO[g] + x1 * fWO[g + 1];
                }
            #pragma unroll
            for (int i = 0; i < 2; i++) {
                racc[i] += __shfl_xor_sync(0xffffffffu, racc[i], 1);
                racc[i] += __shfl_xor_sync(0xffffffffu, racc[i], 2);
            }
            if (wn == 0 && (lane & 3) == 0) {
                fQ[rbase] = racc[0];
                fQ[rbase + 8] = racc[1];
            }
            __syncthreads();
            if (wn == 1 && (lane & 3) == 0) {
                #pragma unroll
                for (int i = 0; i < 2; i++) {
                    const int row = rbase + i * 8;
                    const int t = base + row;
                    if (t < 200) {
                        float lg = fQ[row] + racc[i] + bout[0];
                        if (mask[(size_t)b * 200 + t] == 0) lg = MASK_PAD;
                        fLOG[t] = lg;
                    }
                }
            }
            __syncthreads();
        }
    }

    // ---- softmax over 200 logits (16 warps) ----
    float v = (tid < 200) ? fLOG[tid] : -3.4e38f;
    float m = v;
    #pragma unroll
    for (int o = 16; o > 0; o >>= 1)
        m = fmaxf(m, __shfl_xor_sync(0xffffffffu, m, o));
    if (lane == 0) fRED[wid] = m;
    __syncthreads();
    float mx = fRED[0];
    #pragma unroll
    for (int i = 1; i < 16; i++) mx = fmaxf(mx, fRED[i]);
    float e = (tid < 200) ? expf(v - mx) : 0.f;
    float s = e;
    #pragma unroll
    for (int o = 16; o > 0; o >>= 1)
        s += __shfl_xor_sync(0xffffffffu, s, o);
    __syncthreads();
    if (lane == 0) fRED[wid] = s;
    __syncthreads();
    float tot = 0.f;
    #pragma unroll
    for (int i = 0; i < 16; i++) tot += fRED[i];
    if (tid < 200) fLOG[tid] = e / tot;
    __syncthreads();

    // ---- out[b,:] = attn @ V  (4-way split over t) ----
    float* scr = (float*)(smb + SMB_AH);
    const int quarter = tid >> 7;        // 0..3 -> t chunks of 50
    const int dch = tid & 127;
    const float* vb = val + ((size_t)b * 200 + quarter * 50) * 128 + dch;
    const float* at = &fLOG[quarter * 50];
    float s0 = 0.f, s1 = 0.f;
    #pragma unroll 5
    for (int t = 0; t < 50; t += 2) {
        s0 += at[t + 0] * vb[(size_t)(t + 0) * 128];
        s1 += at[t + 1] * vb[(size_t)(t + 1) * 128];
    }
    scr[tid] = s0 + s1;
    __syncthreads();
    if (tid < 128)
        out[(size_t)b * 128 + tid] =
            (scr[tid] + scr[tid + 128]) + (scr[tid + 256] + scr[tid + 384]);
}

extern "C" void kernel_launch(void* const* d_in, const int* in_sizes, int n_in,
                              void* d_out, int out_size) {
    (void)in_sizes; (void)n_in; (void)out_size;
    const float* query = (const float*)d_in[0];
    const float* key   = (const float*)d_in[1];
    const float* val   = (const float*)d_in[2];
    const int*   mask  = (const int*)d_in[3];
    const float* W0    = (const float*)d_in[4];
    const float* b0    = (const float*)d_in[5];
    const float* a0    = (const float*)d_in[6];
    const float* W1    = (const float*)d_in[7];
    const float* b1    = (const float*)d_in[8];
    const float* a1    = (const float*)d_in[9];
    const float* Wout  = (const float*)d_in[10];
    const float* bout  = (const float*)d_in[11];
    float* out = (float*)d_out;

    cudaFuncSetAttribute(din4_kernel, cudaFuncAttributeMaxDynamicSharedMemorySize,
                         SMB_TOT);
    prep_kernel<<<64, 256>>>(W0);
    din4_kernel<<<2048, NTHR, SMB_TOT>>>(query, key, val, mask, W0, b0, a0,
                                         W1, b1, a1, Wout, bout, out);
}

// round 8
// speedup vs baseline: 1.6236x; 1.3148x over previous
#include <cuda_runtime.h>
#include <cuda_bf16.h>
#include <cstdint>

#define MASK_PAD (-4294967295.0f)

// ---------------- byte offsets in dynamic SMEM ----------------
// fp32/tf32 tiles, row stride 528 B (132 floats): bank(r,c) = (4r+c) mod 32,
// conflict-free for the (lane>>2, lane&3) fragment access pattern.
#define AROW 528
#define SMB_BM   0                          // M^T: 128 x 528            = 67584
#define SMB_W1   67584                      // W1^T: 64 x 528            = 33792
#define SMB_A    101376                     // 2 halves x 64 x 528       = 67584
#define AHALF    33792
#define SMB_C    168960                     // c vec, 128 f
#define SMB_B1   169472                     // 64 f
#define SMB_WOUT 169728                     // 64 f
#define SMB_P    169984                     // logit partials 4x128 f    = 2048
#define SMB_LOG  172032                     // 208 f
#define SMB_RED  172864                     // 16 f
#define SMB_MASK 172928                     // 200 ints
#define SMB_TOT  173760

#define NTHR 512

__device__ float g_W0bc[128 * 128];   // W0b - W0c
__device__ float g_W0ac[128 * 128];   // W0a + W0c

__global__ void prep_kernel(const float* __restrict__ W0) {
    int idx = blockIdx.x * blockDim.x + threadIdx.x;
    if (idx < 128 * 128) {
        int i = idx >> 7, j = idx & 127;
        float wa = W0[i * 128 + j];
        float wb = W0[(128 + i) * 128 + j];
        float wc = W0[(256 + i) * 128 + j];
        g_W0bc[idx] = wb - wc;
        g_W0ac[idx] = wa + wc;
    }
}

__device__ __forceinline__ uint32_t tf32r(float x) {
    uint32_t u;
    asm("cvt.rna.tf32.f32 %0, %1;" : "=r"(u) : "f"(x));
    return u;
}
__device__ __forceinline__ void mma_tf32(float* c, const uint32_t* a, const uint32_t* b) {
    asm volatile("mma.sync.aligned.m16n8k8.row.col.f32.tf32.tf32.f32 "
                 "{%0,%1,%2,%3}, {%4,%5,%6,%7}, {%8,%9}, {%0,%1,%2,%3};"
                 : "+f"(c[0]), "+f"(c[1]), "+f"(c[2]), "+f"(c[3])
                 : "r"(a[0]), "r"(a[1]), "r"(a[2]), "r"(a[3]), "r"(b[0]), "r"(b[1]));
}
__device__ __forceinline__ uint32_t lds32(const char* p) {
    return *(const uint32_t*)p;
}
__device__ __forceinline__ void barh(int hid) {
    asm volatile("bar.sync %0, 256;" :: "r"(1 + hid) : "memory");
}

__global__ void __launch_bounds__(NTHR, 1)
din5_kernel(const float* __restrict__ query, const float* __restrict__ key,
            const float* __restrict__ val, const int* __restrict__ mask,
            const float* __restrict__ W0, const float* __restrict__ b0,
            const float* __restrict__ a0, const float* __restrict__ W1,
            const float* __restrict__ b1, const float* __restrict__ a1,
            const float* __restrict__ Wout, const float* __restrict__ bout,
            float* __restrict__ out) {
    extern __shared__ char smb[];
    const int tid = threadIdx.x;
    const int lane = tid & 31;
    const int wid = tid >> 5;            // 0..15
    const int b = blockIdx.x;
    float* fC   = (float*)(smb + SMB_C);
    float* fB1  = (float*)(smb + SMB_B1);
    float* fWO  = (float*)(smb + SMB_WOUT);
    float* fP   = (float*)(smb + SMB_P);
    float* fLOG = (float*)(smb + SMB_LOG);
    float* fRED = (float*)(smb + SMB_RED);
    int*   iMSK = (int*)(smb + SMB_MASK);
    float* fQ   = fP;                    // reuse partial region for q during setup

    if (tid < 128) fQ[tid] = query[(size_t)b * 128 + tid];
    if (tid < 64) { fB1[tid] = b1[tid]; fWO[tid] = Wout[tid]; }
    if (tid >= 256 && tid < 456) iMSK[tid - 256] = mask[(size_t)b * 200 + (tid - 256)];
    __syncthreads();

    // ---- build M^T (rows h, cols k), tf32-rounded fp32 ----
    const float* W0d = W0 + 384 * 128;
    #pragma unroll
    for (int p = 0; p < 32; p++) {                 // 16384 elems
        int idx = tid + p * NTHR;
        int k = idx >> 7, h = idx & 127;
        float m = g_W0bc[k * 128 + h] + fQ[k] * W0d[k * 128 + h];
        *(uint32_t*)(smb + SMB_BM + h * AROW + k * 4) = tf32r(m);
    }
    // ---- build W1^T (rows g, cols h) ----
    #pragma unroll
    for (int p = 0; p < 16; p++) {                 // 8192 elems
        int idx = tid + p * NTHR;
        int h = idx >> 6, g = idx & 63;
        *(uint32_t*)(smb + SMB_W1 + g * AROW + h * 4) = tf32r(W1[h * 64 + g]);
    }
    // ---- c = q @ (W0a+W0c) + b0 (fp32 exact) ----
    float cval = 0.f;
    if (tid < 128) {
        float s0 = 0.f, s1 = 0.f, s2 = 0.f, s3 = 0.f;
        for (int i = 0; i < 128; i += 4) {
            s0 += fQ[i + 0] * g_W0ac[(i + 0) * 128 + tid];
            s1 += fQ[i + 1] * g_W0ac[(i + 1) * 128 + tid];
            s2 += fQ[i + 2] * g_W0ac[(i + 2) * 128 + tid];
            s3 += fQ[i + 3] * g_W0ac[(i + 3) * 128 + tid];
        }
        cval = (s0 + s1) + (s2 + s3) + b0[tid];
    }
    __syncthreads();                // fQ (=fP) reads done
    if (tid < 128) fC[tid] = cval;
    __syncthreads();

    // ---- two independent 8-warp halves ----
    const int hid = tid >> 8;            // 0/1
    const int htid = tid & 255;
    const int hw = wid & 7;
    const int wm = hw & 1;               // 32-row group within 64-row tile
    const int wn = hw >> 1;              // 0..3
    char* Ah = smb + SMB_A + hid * AHALF;

    const uint32_t aoff = (uint32_t)((wm * 32 + (lane >> 2)) * AROW + (lane & 3) * 4);
    const uint32_t boff1 = (uint32_t)(((lane >> 2)) * AROW + (lane & 3) * 4);
    const int rb = wm * 32 + (lane >> 2);

    for (int ti = 0; ti < 2; ti++) {
        const int tbase = (hid * 2 + ti) * 64;

        // ---- load K tile (64 rows) -> A half region, tf32-rounded ----
        #pragma unroll
        for (int p = 0; p < 8; p++) {
            int f4 = htid + p * 256;         // 2048 float4 slots
            int row = f4 >> 5;
            int c4 = (f4 & 31) << 2;
            int t = tbase + row;
            float4 v = make_float4(0.f, 0.f, 0.f, 0.f);
            if (t < 200) v = *(const float4*)&key[((size_t)b * 200 + t) * 128 + c4];
            uint4 u;
            u.x = tf32r(v.x); u.y = tf32r(v.y); u.z = tf32r(v.z); u.w = tf32r(v.w);
            *(uint4*)(Ah + row * AROW + c4 * 4) = u;
        }
        barh(hid);

        // ---- GEMM1: 32x32 warp tile, tf32, 16 k-steps ----
        float acc[2][4][4];
        #pragma unroll
        for (int mi = 0; mi < 2; mi++)
            #pragma unroll
            for (int ni = 0; ni < 4; ni++)
                #pragma unroll
                for (int q = 0; q < 4; q++) acc[mi][ni][q] = 0.f;
        {
            const char* Bp = smb + SMB_BM + wn * 32 * AROW;
            #pragma unroll 4
            for (int k = 0; k < 16; k++) {
                uint32_t af[2][4];
                #pragma unroll
                for (int mi = 0; mi < 2; mi++) {
                    const char* ap = Ah + aoff + mi * 16 * AROW + k * 32;
                    af[mi][0] = lds32(ap);
                    af[mi][1] = lds32(ap + 8 * AROW);
                    af[mi][2] = lds32(ap + 16);
                    af[mi][3] = lds32(ap + 8 * AROW + 16);
                }
                uint32_t bf[4][2];
                #pragma unroll
                for (int ni = 0; ni < 4; ni++) {
                    const char* bp = Bp + boff1 + ni * 8 * AROW + k * 32;
                    bf[ni][0] = lds32(bp);
                    bf[ni][1] = lds32(bp + 16);
                }
                #pragma unroll
                for (int mi = 0; mi < 2; mi++)
                    #pragma unroll
                    for (int ni = 0; ni < 4; ni++)
                        mma_tf32(acc[mi][ni], af[mi], bf[ni]);
            }
        }
        barh(hid);     // K reads done before H0 overwrite

        // ---- epilogue1: +c, PReLU(a0), tf32-round -> A half region ----
        #pragma unroll
        for (int mi = 0; mi < 2; mi++)
            #pragma unroll
            for (int ni = 0; ni < 4; ni++)
                #pragma unroll
                for (int rr = 0; rr < 2; rr++) {
                    const int row = rb + mi * 16 + rr * 8;
                    const int t = tbase + row;
                    const int col = wn * 32 + ni * 8 + (lane & 3) * 2;
                    float x0 = acc[mi][ni][rr * 2 + 0] + fC[col];
                    float x1 = acc[mi][ni][rr * 2 + 1] + fC[col + 1];
                    if (x0 < 0.f) x0 *= (t < 200 ? __ldg(&a0[t * 128 + col]) : 0.25f);
                    if (x1 < 0.f) x1 *= (t < 200 ? __ldg(&a0[t * 128 + col + 1]) : 0.25f);
                    uint2 u; u.x = tf32r(x0); u.y = tf32r(x1);
                    *(uint2*)(Ah + row * AROW + col * 4) = u;
                }
        barh(hid);

        // ---- GEMM2: 32x16 warp tile ----
        float acc2[2][2][4];
        #pragma unroll
        for (int mi = 0; mi < 2; mi++)
            #pragma unroll
            for (int ni = 0; ni < 2; ni++)
                #pragma unroll
                for (int q = 0; q < 4; q++) acc2[mi][ni][q] = 0.f;
        {
            const char* Bp = smb + SMB_W1 + wn * 16 * AROW;
            #pragma unroll 4
            for (int k = 0; k < 16; k++) {
                uint32_t af[2][4];
                #pragma unroll
                for (int mi = 0; mi < 2; mi++) {
                    const char* ap = Ah + aoff + mi * 16 * AROW + k * 32;
                    af[mi][0] = lds32(ap);
                    af[mi][1] = lds32(ap + 8 * AROW);
                    af[mi][2] = lds32(ap + 16);
                    af[mi][3] = lds32(ap + 8 * AROW + 16);
                }
                uint32_t bf[2][2];
                #pragma unroll
                for (int ni = 0; ni < 2; ni++) {
                    const char* bp = Bp + boff1 + ni * 8 * AROW + k * 32;
                    bf[ni][0] = lds32(bp);
                    bf[ni][1] = lds32(bp + 16);
                }
                #pragma unroll
                for (int mi = 0; mi < 2; mi++)
                    #pragma unroll
                    for (int ni = 0; ni < 2; ni++)
                        mma_tf32(acc2[mi][ni], af[mi], bf[ni]);
            }
        }

        // ---- epilogue2: +b1, PReLU(a1), dot Wout -> per-wn partials ----
        {
            float racc[4] = {0.f, 0.f, 0.f, 0.f};
            #pragma unroll
            for (int mi = 0; mi < 2; mi++)
                #pragma unroll
                for (int ni = 0; ni < 2; ni++)
                    #pragma unroll
                    for (int rr = 0; rr < 2; rr++) {
                        const int row = rb + mi * 16 + rr * 8;
                        const int t = tbase + row;
                        const int g = wn * 16 + ni * 8 + (lane & 3) * 2;
                        float x0 = acc2[mi][ni][rr * 2 + 0] + fB1[g];
                        float x1 = acc2[mi][ni][rr * 2 + 1] + fB1[g + 1];
                        if (x0 < 0.f) x0 *= (t < 200 ? __ldg(&a1[t * 64 + g]) : 0.25f);
                        if (x1 < 0.f) x1 *= (t < 200 ? __ldg(&a1[t * 64 + g + 1]) : 0.25f);
                        racc[mi * 2 + rr] += x0 * fWO[g] + x1 * fWO[g + 1];
                    }
            #pragma unroll
            for (int i = 0; i < 4; i++) {
                racc[i] += __shfl_xor_sync(0xffffffffu, racc[i], 1);
                racc[i] += __shfl_xor_sync(0xffffffffu, racc[i], 2);
            }
            if ((lane & 3) == 0) {
                #pragma unroll
                for (int i = 0; i < 4; i++) {
                    const int row = rb + (i >> 1) * 16 + (i & 1) * 8;
                    fP[wn * 128 + hid * 64 + row] = racc[i];
                }
            }
            barh(hid);
            if (htid < 64) {
                const int row = htid;
                const int t = tbase + row;
                if (t < 200) {
                    const int ix = hid * 64 + row;
                    float lg = ((fP[ix] + fP[128 + ix]) + (fP[256 + ix] + fP[384 + ix]))
                               + bout[0];
                    if (iMSK[t] == 0) lg = MASK_PAD;
                    fLOG[t] = lg;
                }
            }
            barh(hid);   // fP reads done before next tile's partial writes
        }
    }

    __syncthreads();

    // ---- softmax over 200 logits (16 warps) ----
    float v = (tid < 200) ? fLOG[tid] : -3.4e38f;
    float m = v;
    #pragma unroll
    for (int o = 16; o > 0; o >>= 1)
        m = fmaxf(m, __shfl_xor_sync(0xffffffffu, m, o));
    if (lane == 0) fRED[wid] = m;
    __syncthreads();
    float mx = fRED[0];
    #pragma unroll
    for (int i = 1; i < 16; i++) mx = fmaxf(mx, fRED[i]);
    float e = (tid < 200) ? expf(v - mx) : 0.f;
    float s = e;
    #pragma unroll
    for (int o = 16; o > 0; o >>= 1)
        s += __shfl_xor_sync(0xffffffffu, s, o);
    __syncthreads();
    if (lane == 0) fRED[wid] = s;
    __syncthreads();
    float tot = 0.f;
    #pragma unroll
    for (int i = 0; i < 16; i++) tot += fRED[i];
    if (tid < 200) fLOG[tid] = e / tot;
    __syncthreads();

    // ---- out[b,:] = attn @ V  (4-way split over t) ----
    float* scr = (float*)(smb + SMB_A);
    const int quarter = tid >> 7;        // 0..3 -> t chunks of 50
    const int dch = tid & 127;
    const float* vb = val + ((size_t)b * 200 + quarter * 50) * 128 + dch;
    const float* at = &fLOG[quarter * 50];
    float s0 = 0.f, s1 = 0.f;
    #pragma unroll 5
    for (int t = 0; t < 50; t += 2) {
        s0 += at[t + 0] * vb[(size_t)(t + 0) * 128];
        s1 += at[t + 1] * vb[(size_t)(t + 1) * 128];
    }
    scr[tid] = s0 + s1;
    __syncthreads();
    if (tid < 128)
        out[(size_t)b * 128 + tid] =
            (scr[tid] + scr[tid + 128]) + (scr[tid + 256] + scr[tid + 384]);
}

extern "C" void kernel_launch(void* const* d_in, const int* in_sizes, int n_in,
                              void* d_out, int out_size) {
    (void)in_sizes; (void)n_in; (void)out_size;
    const float* query = (const float*)d_in[0];
    const float* key   = (const float*)d_in[1];
    const float* val   = (const float*)d_in[2];
    const int*   mask  = (const int*)d_in[3];
    const float* W0    = (const float*)d_in[4];
    const float* b0    = (const float*)d_in[5];
    const float* a0    = (const float*)d_in[6];
    const float* W1    = (const float*)d_in[7];
    const float* b1    = (const float*)d_in[8];
    const float* a1    = (const float*)d_in[9];
    const float* Wout  = (const float*)d_in[10];
    const float* bout  = (const float*)d_in[11];
    float* out = (float*)d_out;

    cudaFuncSetAttribute(din5_kernel, cudaFuncAttributeMaxDynamicSharedMemorySize,
                         SMB_TOT);
    prep_kernel<<<64, 256>>>(W0);
    din5_kernel<<<2048, NTHR, SMB_TOT>>>(query, key, val, mask, W0, b0, a0,
                                         W1, b1, a1, Wout, bout, out);
}

// round 12
// speedup vs baseline: 2.5458x; 1.5680x over previous
#include <cuda_runtime.h>
#include <cuda_bf16.h>
#include <cstdint>

#define MASK_PAD (-4294967295.0f)

// ---------------- byte offsets in dynamic SMEM ----------------
// fp32/tf32 tiles, row stride 528 B (132 floats): bank(r,c) = (4r+c) mod 32,
// conflict-free for the (lane>>2, lane&3) fragment access pattern.
#define AROW 528
#define SMB_BM   0                          // M^T: 128 x 528            = 67584
#define SMB_W1   67584                      // W1^T: 64 x 528            = 33792
#define SMB_A    101376                     // 2 halves x 64 x 528       = 67584
#define AHALF    33792
#define SMB_C    168960                     // c vec, 128 f
#define SMB_B1   169472                     // 64 f
#define SMB_WOUT 169728                     // 64 f
#define SMB_P    169984                     // logit partials 4x128 f    = 2048
#define SMB_LOG  172032                     // 208 f
#define SMB_RED  172864                     // 16 f
#define SMB_MASK 172928                     // 200 ints
#define SMB_TOT  173760

#define NTHR 512

__device__ float g_W0bc[128 * 128];   // W0b - W0c
__device__ float g_W0ac[128 * 128];   // W0a + W0c

__global__ void prep_kernel(const float* __restrict__ W0) {
    int idx = blockIdx.x * blockDim.x + threadIdx.x;
    if (idx < 128 * 128) {
        int i = idx >> 7, j = idx & 127;
        float wa = W0[i * 128 + j];
        float wb = W0[(128 + i) * 128 + j];
        float wc = W0[(256 + i) * 128 + j];
        g_W0bc[idx] = wb - wc;
        g_W0ac[idx] = wa + wc;
    }
}

__device__ __forceinline__ uint32_t tf32r(float x) {
    uint32_t u;
    asm("cvt.rna.tf32.f32 %0, %1;" : "=r"(u) : "f"(x));
    return u;
}
__device__ __forceinline__ void mma_tf32(float* c, const uint32_t* a, const uint32_t* b) {
    asm volatile("mma.sync.aligned.m16n8k8.row.col.f32.tf32.tf32.f32 "
                 "{%0,%1,%2,%3}, {%4,%5,%6,%7}, {%8,%9}, {%0,%1,%2,%3};"
                 : "+f"(c[0]), "+f"(c[1]), "+f"(c[2]), "+f"(c[3])
                 : "r"(a[0]), "r"(a[1]), "r"(a[2]), "r"(a[3]), "r"(b[0]), "r"(b[1]));
}
__device__ __forceinline__ uint32_t lds32(const char* p) {
    return *(const uint32_t*)p;
}
__device__ __forceinline__ void barh(int hid) {
    asm volatile("bar.sync %0, 256;" :: "r"(1 + hid) : "memory");
}
__device__ __forceinline__ void l2pf(const void* p) {
    asm volatile("prefetch.global.L2 [%0];" :: "l"(p));
}

__global__ void __launch_bounds__(NTHR, 1)
din6_kernel(const float* __restrict__ query, const float* __restrict__ key,
            const float* __restrict__ val, const int* __restrict__ mask,
            const float* __restrict__ W0, const float* __restrict__ b0,
            const float* __restrict__ a0, const float* __restrict__ W1,
            const float* __restrict__ b1, const float* __restrict__ a1,
            const float* __restrict__ Wout, const float* __restrict__ bout,
            float* __restrict__ out) {
    extern __shared__ char smb[];
    const int tid = threadIdx.x;
    const int lane = tid & 31;
    const int wid = tid >> 5;            // 0..15
    const int b = blockIdx.x;
    float* fC   = (float*)(smb + SMB_C);
    float* fB1  = (float*)(smb + SMB_B1);
    float* fWO  = (float*)(smb + SMB_WOUT);
    float* fP   = (float*)(smb + SMB_P);
    float* fLOG = (float*)(smb + SMB_LOG);
    float* fRED = (float*)(smb + SMB_RED);
    int*   iMSK = (int*)(smb + SMB_MASK);
    float* fQ   = fP;                    // reuse partial region for q during setup

    if (tid < 128) fQ[tid] = query[(size_t)b * 128 + tid];
    if (tid < 64) { fB1[tid] = b1[tid]; fWO[tid] = Wout[tid]; }
    if (tid >= 256 && tid < 456) iMSK[tid - 256] = mask[(size_t)b * 200 + (tid - 256)];
    const float boutv = __ldg(bout);

    // warm L2 with this batch's V (used at the very end)
    {
        const char* vbase = (const char*)(val + (size_t)b * 200 * 128);
        const char* p0 = vbase + (size_t)tid * 128;
        if (tid * 128 < 102400) l2pf(p0);
        if ((tid + 512) * 128 < 102400) l2pf(p0 + 512 * 128);
    }
    __syncthreads();

    // ---- build M^T (rows h, cols k), tf32-rounded fp32 ----
    const float* W0d = W0 + 384 * 128;
    #pragma unroll
    for (int p = 0; p < 32; p++) {                 // 16384 elems
        int idx = tid + p * NTHR;
        int k = idx >> 7, h = idx & 127;
        float m = g_W0bc[k * 128 + h] + fQ[k] * W0d[k * 128 + h];
        *(uint32_t*)(smb + SMB_BM + h * AROW + k * 4) = tf32r(m);
    }
    // ---- build W1^T (rows g, cols h) ----
    #pragma unroll
    for (int p = 0; p < 16; p++) {                 // 8192 elems
        int idx = tid + p * NTHR;
        int h = idx >> 6, g = idx & 63;
        *(uint32_t*)(smb + SMB_W1 + g * AROW + h * 4) = tf32r(W1[h * 64 + g]);
    }
    // ---- c = q @ (W0a+W0c) + b0 (fp32 exact) ----
    float cval = 0.f;
    if (tid < 128) {
        float s0 = 0.f, s1 = 0.f, s2 = 0.f, s3 = 0.f;
        for (int i = 0; i < 128; i += 4) {
            s0 += fQ[i + 0] * g_W0ac[(i + 0) * 128 + tid];
            s1 += fQ[i + 1] * g_W0ac[(i + 1) * 128 + tid];
            s2 += fQ[i + 2] * g_W0ac[(i + 2) * 128 + tid];
            s3 += fQ[i + 3] * g_W0ac[(i + 3) * 128 + tid];
        }
        cval = (s0 + s1) + (s2 + s3) + b0[tid];
    }
    __syncthreads();                // fQ (=fP) reads done
    if (tid < 128) fC[tid] = cval;
    __syncthreads();

    // ---- two independent 8-warp halves ----
    const int hid = tid >> 8;            // 0/1
    const int htid = tid & 255;
    const int hw = wid & 7;
    const int wm = hw & 1;               // 32-row group within 64-row tile
    const int wn = hw >> 1;              // 0..3
    char* Ah = smb + SMB_A + hid * AHALF;

    const uint32_t aoff = (uint32_t)((wm * 32 + (lane >> 2)) * AROW + (lane & 3) * 4);
    const uint32_t boff1 = (uint32_t)(((lane >> 2)) * AROW + (lane & 3) * 4);
    const int rb = wm * 32 + (lane >> 2);

    for (int ti = 0; ti < 2; ti++) {
        const int tbase = (hid * 2 + ti) * 64;

        // ---- load K tile (64 rows) -> A half region, tf32-rounded ----
        #pragma unroll
        for (int p = 0; p < 8; p++) {
            int f4 = htid + p * 256;         // 2048 float4 slots
            int row = f4 >> 5;
            int c4 = (f4 & 31) << 2;
            int t = tbase + row;
            float4 v = make_float4(0.f, 0.f, 0.f, 0.f);
            if (t < 200) v = *(const float4*)&key[((size_t)b * 200 + t) * 128 + c4];
            uint4 u;
            u.x = tf32r(v.x); u.y = tf32r(v.y); u.z = tf32r(v.z); u.w = tf32r(v.w);
            *(uint4*)(Ah + row * AROW + c4 * 4) = u;
        }

        // ---- prefetch epi1 alphas (independent of MMA; latency hides under GEMM1)
        float2 al0[16];
        #pragma unroll
        for (int mi = 0; mi < 2; mi++)
            #pragma unroll
            for (int rr = 0; rr < 2; rr++)
                #pragma unroll
                for (int ni = 0; ni < 4; ni++) {
                    int t = tbase + rb + mi * 16 + rr * 8;
                    int tc = t < 200 ? t : 199;
                    int col = wn * 32 + ni * 8 + (lane & 3) * 2;
                    al0[(mi * 2 + rr) * 4 + ni] =
                        __ldg((const float2*)&a0[tc * 128 + col]);
                }
        barh(hid);

        // ---- GEMM1: 32x32 warp tile, tf32, 16 k-steps ----
        float acc[2][4][4];
        #pragma unroll
        for (int mi = 0; mi < 2; mi++)
            #pragma unroll
            for (int ni = 0; ni < 4; ni++)
                #pragma unroll
                for (int q = 0; q < 4; q++) acc[mi][ni][q] = 0.f;
        {
            const char* Bp = smb + SMB_BM + wn * 32 * AROW;
            #pragma unroll 4
            for (int k = 0; k < 16; k++) {
                uint32_t af[2][4];
                #pragma unroll
                for (int mi = 0; mi < 2; mi++) {
                    const char* ap = Ah + aoff + mi * 16 * AROW + k * 32;
                    af[mi][0] = lds32(ap);
                    af[mi][1] = lds32(ap + 8 * AROW);
                    af[mi][2] = lds32(ap + 16);
                    af[mi][3] = lds32(ap + 8 * AROW + 16);
                }
                uint32_t bf[4][2];
                #pragma unroll
                for (int ni = 0; ni < 4; ni++) {
                    const char* bp = Bp + boff1 + ni * 8 * AROW + k * 32;
                    bf[ni][0] = lds32(bp);
                    bf[ni][1] = lds32(bp + 16);
                }
                #pragma unroll
                for (int mi = 0; mi < 2; mi++)
                    #pragma unroll
                    for (int ni = 0; ni < 4; ni++)
                        mma_tf32(acc[mi][ni], af[mi], bf[ni]);
            }
        }
        barh(hid);     // K reads done before H0 overwrite

        // ---- epilogue1: +c, PReLU(a0), tf32-round -> A half region ----
        #pragma unroll
        for (int mi = 0; mi < 2; mi++)
            #pragma unroll
            for (int ni = 0; ni < 4; ni++)
                #pragma unroll
                for (int rr = 0; rr < 2; rr++) {
                    const int row = rb + mi * 16 + rr * 8;
                    const int col = wn * 32 + ni * 8 + (lane & 3) * 2;
                    const float2 al = al0[(mi * 2 + rr) * 4 + ni];
                    float x0 = acc[mi][ni][rr * 2 + 0] + fC[col];
                    float x1 = acc[mi][ni][rr * 2 + 1] + fC[col + 1];
                    if (x0 < 0.f) x0 *= al.x;
                    if (x1 < 0.f) x1 *= al.y;
                    uint2 u; u.x = tf32r(x0); u.y = tf32r(x1);
                    *(uint2*)(Ah + row * AROW + col * 4) = u;
                }

        // ---- prefetch epi2 alphas (hide under GEMM2) ----
        float2 al1[8];
        #pragma unroll
        for (int mi = 0; mi < 2; mi++)
            #pragma unroll
            for (int rr = 0; rr < 2; rr++)
                #pragma unroll
                for (int ni = 0; ni < 2; ni++) {
                    int t = tbase + rb + mi * 16 + rr * 8;
                    int tc = t < 200 ? t : 199;
                    int g = wn * 16 + ni * 8 + (lane & 3) * 2;
                    al1[(mi * 2 + rr) * 2 + ni] =
                        __ldg((const float2*)&a1[tc * 64 + g]);
                }
        barh(hid);

        // ---- GEMM2: 32x16 warp tile ----
        float acc2[2][2][4];
        #pragma unroll
        for (int mi = 0; mi < 2; mi++)
            #pragma unroll
            for (int ni = 0; ni < 2; ni++)
                #pragma unroll
                for (int q = 0; q < 4; q++) acc2[mi][ni][q] = 0.f;
        {
            const char* Bp = smb + SMB_W1 + wn * 16 * AROW;
            #pragma unroll 4
            for (int k = 0; k < 16; k++) {
                uint32_t af[2][4];
                #pragma unroll
                for (int mi = 0; mi < 2; mi++) {
                    const char* ap = Ah + aoff + mi * 16 * AROW + k * 32;
                    af[mi][0] = lds32(ap);
                    af[mi][1] = lds32(ap + 8 * AROW);
                    af[mi][2] = lds32(ap + 16);
                    af[mi][3] = lds32(ap + 8 * AROW + 16);
                }
                uint32_t bf[2][2];
                #pragma unroll
                for (int ni = 0; ni < 2; ni++) {
                    const char* bp = Bp + boff1 + ni * 8 * AROW + k * 32;
                    bf[ni][0] = lds32(bp);
                    bf[ni][1] = lds32(bp + 16);
                }
                #pragma unroll
                for (int mi = 0; mi < 2; mi++)
                    #pragma unroll
                    for (int ni = 0; ni < 2; ni++)
                        mma_tf32(acc2[mi][ni], af[mi], bf[ni]);
            }
        }

        // ---- epilogue2: +b1, PReLU(a1), dot Wout -> per-wn partials ----
        {
            float racc[4] = {0.f, 0.f, 0.f, 0.f};
            #pragma unroll
            for (int mi = 0; mi < 2; mi++)
                #pragma unroll
                for (int ni = 0; ni < 2; ni++)
                    #pragma unroll
                    for (int rr = 0; rr < 2; rr++) {
                        const int g = wn * 16 + ni * 8 + (lane & 3) * 2;
                        const float2 al = al1[(mi * 2 + rr) * 2 + ni];
                        float x0 = acc2[mi][ni][rr * 2 + 0] + fB1[g];
                        float x1 = acc2[mi][ni][rr * 2 + 1] + fB1[g + 1];
                        if (x0 < 0.f) x0 *= al.x;
                        if (x1 < 0.f) x1 *= al.y;
                        racc[mi * 2 + rr] += x0 * fWO[g] + x1 * fWO[g + 1];
                    }
            #pragma unroll
            for (int i = 0; i < 4; i++) {
                racc[i] += __shfl_xor_sync(0xffffffffu, racc[i], 1);
                racc[i] += __shfl_xor_sync(0xffffffffu, racc[i], 2);
            }
            if ((lane & 3) == 0) {
                #pragma unroll
                for (int i = 0; i < 4; i++) {
                    const int row = rb + (i >> 1) * 16 + (i & 1) * 8;
                    fP[wn * 128 + hid * 64 + row] = racc[i];
                }
            }
            barh(hid);
            if (htid < 64) {
                const int row = htid;
                const int t = tbase + row;
                if (t < 200) {
                    const int ix = hid * 64 + row;
                    float lg = ((fP[ix] + fP[128 + ix]) + (fP[256 + ix] + fP[384 + ix]))
                               + boutv;
                    if (iMSK[t] == 0) lg = MASK_PAD;
                    fLOG[t] = lg;
                }
            }
            barh(hid);   // fP reads done before next tile's partial writes
        }
    }

    __syncthreads();

    // ---- softmax over 200 logits (16 warps) ----
    float v = (tid < 200) ? fLOG[tid] : -3.4e38f;
    float m = v;
    #pragma unroll
    for (int o = 16; o > 0; o >>= 1)
        m = fmaxf(m, __shfl_xor_sync(0xffffffffu, m, o));
    if (lane == 0) fRED[wid] = m;
    __syncthreads();
    float mx = fRED[0];
    #pragma unroll
    for (int i = 1; i < 16; i++) mx = fmaxf(mx, fRED[i]);
    float e = (tid < 200) ? __expf(v - mx) : 0.f;
    float s = e;
    #pragma unroll
    for (int o = 16; o > 0; o >>= 1)
        s += __shfl_xor_sync(0xffffffffu, s, o);
    __syncthreads();
    if (lane == 0) fRED[wid] = s;
    __syncthreads();
    float tot = 0.f;
    #pragma unroll
    for (int i = 0; i < 16; i++) tot += fRED[i];
    if (tid < 200) fLOG[tid] = e / tot;
    __syncthreads();

    // ---- out[b,:] = attn @ V  (4-way split over t) ----
    float* scr = (float*)(smb + SMB_A);
    const int quarter = tid >> 7;        // 0..3 -> t chunks of 50
    const int dch = tid & 127;
    const float* vb = val + ((size_t)b * 200 + quarter * 50) * 128 + dch;
    const float* at = &fLOG[quarter * 50];
    float s0 = 0.f, s1 = 0.f;
    #pragma unroll 5
    for (int t = 0; t < 50; t += 2) {
        s0 += at[t + 0] * vb[(size_t)(t + 0) * 128];
        s1 += at[t + 1] * vb[(size_t)(t + 1) * 128];
    }
    scr[tid] = s0 + s1;
    __syncthreads();
    if (tid < 128)
        out[(size_t)b * 128 + tid] =
            (scr[tid] + scr[tid + 128]) + (scr[tid + 256] + scr[tid + 384]);
}

extern "C" void kernel_launch(void* const* d_in, const int* in_sizes, int n_in,
                              void* d_out, int out_size) {
    (void)in_sizes; (void)n_in; (void)out_size;
    const float* query = (const float*)d_in[0];
    const float* key   = (const float*)d_in[1];
    const float* val   = (const float*)d_in[2];
    const int*   mask  = (const int*)d_in[3];
    const float* W0    = (const float*)d_in[4];
    const float* b0    = (const float*)d_in[5];
    const float* a0    = (const float*)d_in[6];
    const float* W1    = (const float*)d_in[7];
    const float* b1    = (const float*)d_in[8];
    const float* a1    = (const float*)d_in[9];
    const float* Wout  = (const float*)d_in[10];
    const float* bout  = (const float*)d_in[11];
    float* out = (float*)d_out;

    cudaFuncSetAttribute(din6_kernel, cudaFuncAttributeMaxDynamicSharedMemorySize,
                         SMB_TOT);
    prep_kernel<<<64, 256>>>(W0);
    din6_kernel<<<2048, NTHR, SMB_TOT>>>(query, key, val, mask, W0, b0, a0,
                                         W1, b1, a1, Wout, bout, out);
}

// round 15
// speedup vs baseline: 2.5739x; 1.0110x over previous
#include <cuda_runtime.h>
#include <cuda_bf16.h>
#include <cstdint>

#define MASK_PAD (-4294967295.0f)

#define AROW 528
#define SMB_BM   0
#define SMB_W1   67584
#define SMB_A    101376
#define AHALF    33792
#define SMB_C    168960
#define SMB_B1   169472
#define SMB_WOUT 169728
#define SMB_P    169984
#define SMB_LOG  172032
#define SMB_RED  172864
#define SMB_MASK 172928
#define SMB_TOT  173760

#define NTHR 512

__device__ float g_W0bc[128 * 128];   // W0b - W0c
__device__ float g_W0ac[128 * 128];   // W0a + W0c

__global__ void prep_kernel(const float* __restrict__ W0) {
    int idx = blockIdx.x * blockDim.x + threadIdx.x;
    if (idx < 128 * 128) {
        int i = idx >> 7, j = idx & 127;
        float wa = W0[i * 128 + j];
        float wb = W0[(128 + i) * 128 + j];
        float wc = W0[(256 + i) * 128 + j];
        g_W0bc[idx] = wb - wc;
        g_W0ac[idx] = wa + wc;
    }
}

__device__ __forceinline__ uint32_t tf32r(float x) {
    uint32_t u;
    asm("cvt.rna.tf32.f32 %0, %1;" : "=r"(u) : "f"(x));
    return u;
}
__device__ __forceinline__ void mma_tf32(float* c, const uint32_t* a, const uint32_t* b) {
    asm volatile("mma.sync.aligned.m16n8k8.row.col.f32.tf32.tf32.f32 "
                 "{%0,%1,%2,%3}, {%4,%5,%6,%7}, {%8,%9}, {%0,%1,%2,%3};"
                 : "+f"(c[0]), "+f"(c[1]), "+f"(c[2]), "+f"(c[3])
                 : "r"(a[0]), "r"(a[1]), "r"(a[2]), "r"(a[3]), "r"(b[0]), "r"(b[1]));
}
__device__ __forceinline__ uint32_t lds32(const char* p) {
    return *(const uint32_t*)p;
}
__device__ __forceinline__ void barh(int hid) {
    asm volatile("bar.sync %0, 256;" :: "r"(1 + hid) : "memory");
}
__device__ __forceinline__ void l2pf(const void* p) {
    asm volatile("prefetch.global.L2 [%0];" :: "l"(p));
}

__global__ void __launch_bounds__(NTHR, 1)
din7_kernel(const float* __restrict__ query, const float* __restrict__ key,
            const float* __restrict__ val, const int* __restrict__ mask,
            const float* __restrict__ W0, const float* __restrict__ b0,
            const float* __restrict__ a0, const float* __restrict__ W1,
            const float* __restrict__ b1, const float* __restrict__ a1,
            const float* __restrict__ Wout, const float* __restrict__ bout,
            float* __restrict__ out) {
    extern __shared__ char smb[];
    const int tid = threadIdx.x;
    const int lane = tid & 31;
    const int wid = tid >> 5;            // 0..15
    const int b = blockIdx.x;
    float* fC   = (float*)(smb + SMB_C);
    float* fB1  = (float*)(smb + SMB_B1);
    float* fWO  = (float*)(smb + SMB_WOUT);
    float* fP   = (float*)(smb + SMB_P);
    float* fLOG = (float*)(smb + SMB_LOG);
    float* fRED = (float*)(smb + SMB_RED);
    int*   iMSK = (int*)(smb + SMB_MASK);
    float* fQ   = fP;                    // reuse partial region for q during setup

    if (tid < 128) fQ[tid] = query[(size_t)b * 128 + tid];
    if (tid < 64) { fB1[tid] = b1[tid]; fWO[tid] = Wout[tid]; }
    if (tid >= 256 && tid < 456) iMSK[tid - 256] = mask[(size_t)b * 200 + (tid - 256)];
    const float boutv = __ldg(bout);

    // warm L2 with this batch's K and V slices (102400 B each)
    {
        const char* vbase = (const char*)(val + (size_t)b * 200 * 128);
        const char* kbase = (const char*)(key + (size_t)b * 200 * 128);
        const char* p0 = vbase + (size_t)tid * 128;
        const char* p1 = kbase + (size_t)tid * 128;
        if (tid * 128 < 102400) { l2pf(p0); l2pf(p1); }
        if ((tid + 512) * 128 < 102400) { l2pf(p0 + 512 * 128); l2pf(p1 + 512 * 128); }
    }
    __syncthreads();

    // ---- build M^T (rows h, cols k), tf32-rounded fp32 ----
    const float* W0d = W0 + 384 * 128;
    #pragma unroll
    for (int p = 0; p < 32; p++) {                 // 16384 elems
        int idx = tid + p * NTHR;
        int k = idx >> 7, h = idx & 127;
        float m = g_W0bc[k * 128 + h] + fQ[k] * W0d[k * 128 + h];
        *(uint32_t*)(smb + SMB_BM + h * AROW + k * 4) = tf32r(m);
    }
    // ---- build W1^T (rows g, cols h) ----
    #pragma unroll
    for (int p = 0; p < 16; p++) {                 // 8192 elems
        int idx = tid + p * NTHR;
        int h = idx >> 6, g = idx & 63;
        *(uint32_t*)(smb + SMB_W1 + g * AROW + h * 4) = tf32r(W1[h * 64 + g]);
    }
    // ---- c = q @ (W0a+W0c) + b0 (fp32 exact) ----
    float cval = 0.f;
    if (tid < 128) {
        float s0 = 0.f, s1 = 0.f, s2 = 0.f, s3 = 0.f;
        for (int i = 0; i < 128; i += 4) {
            s0 += fQ[i + 0] * g_W0ac[(i + 0) * 128 + tid];
            s1 += fQ[i + 1] * g_W0ac[(i + 1) * 128 + tid];
            s2 += fQ[i + 2] * g_W0ac[(i + 2) * 128 + tid];
            s3 += fQ[i + 3] * g_W0ac[(i + 3) * 128 + tid];
        }
        cval = (s0 + s1) + (s2 + s3) + b0[tid];
    }
    __syncthreads();                // fQ (=fP) reads done
    if (tid < 128) fC[tid] = cval;
    __syncthreads();

    // ---- two independent 8-warp halves ----
    const int hid = tid >> 8;            // 0/1
    const int htid = tid & 255;
    const int hw = wid & 7;
    const int wm = hw & 1;               // 32-row group within 64-row tile
    const int wn = hw >> 1;              // 0..3
    char* Ah = smb + SMB_A + hid * AHALF;

    const uint32_t aoff = (uint32_t)((wm * 32 + (lane >> 2)) * AROW + (lane & 3) * 4);
    const uint32_t boff1 = (uint32_t)(((lane >> 2)) * AROW + (lane & 3) * 4);
    const int rb = wm * 32 + (lane >> 2);

    for (int ti = 0; ti < 2; ti++) {
        const int tbase = (hid * 2 + ti) * 64;
        const bool shortt = (tbase == 192);           // last tile: 8 live rows
        const int MMAX = shortt ? (wm == 0 ? 1 : 0) : 2;
        const int npgrp = shortt ? 2 : 8;             // K-load: 16 vs 64 rows

        // ---- load K tile -> A half region, tf32-rounded ----
        #pragma unroll
        for (int p = 0; p < 8; p++) {
            if (p < npgrp) {
                int f4 = htid + p * 256;         // f4 slots (32 per row)
                int row = f4 >> 5;
                int c4 = (f4 & 31) << 2;
                int t = tbase + row;
                float4 v = make_float4(0.f, 0.f, 0.f, 0.f);
                if (t < 200) v = *(const float4*)&key[((size_t)b * 200 + t) * 128 + c4];
                uint4 u;
                u.x = tf32r(v.x); u.y = tf32r(v.y); u.z = tf32r(v.z); u.w = tf32r(v.w);
                *(uint4*)(Ah + row * AROW + c4 * 4) = u;
            }
        }

        // ---- prefetch epi1 alphas (latency hides under GEMM1) ----
        float2 al0[16];
        if (MMAX > 0) {
            #pragma unroll
            for (int mi = 0; mi < 2; mi++)
                #pragma unroll
                for (int rr = 0; rr < 2; rr++)
                    #pragma unroll
                    for (int ni = 0; ni < 4; ni++) {
                        int t = tbase + rb + mi * 16 + rr * 8;
                        int tc = t < 200 ? t : 199;
                        int col = wn * 32 + ni * 8 + (lane & 3) * 2;
                        al0[(mi * 2 + rr) * 4 + ni] =
                            __ldg((const float2*)&a0[tc * 128 + col]);
                    }
        }
        barh(hid);

        // ---- GEMM1: 32x32 warp tile, tf32, 16 k-steps ----
        float acc[2][4][4];
        #pragma unroll
        for (int mi = 0; mi < 2; mi++)
            #pragma unroll
            for (int ni = 0; ni < 4; ni++)
                #pragma unroll
                for (int q = 0; q < 4; q++) acc[mi][ni][q] = 0.f;
        if (MMAX > 0) {
            const char* Bp = smb + SMB_BM + wn * 32 * AROW;
            #pragma unroll 4
            for (int k = 0; k < 16; k++) {
                uint32_t af[2][4];
                #pragma unroll
                for (int mi = 0; mi < 2; mi++) {
                    if (mi < MMAX) {
                        const char* ap = Ah + aoff + mi * 16 * AROW + k * 32;
                        af[mi][0] = lds32(ap);
                        af[mi][1] = lds32(ap + 8 * AROW);
                        af[mi][2] = lds32(ap + 16);
                        af[mi][3] = lds32(ap + 8 * AROW + 16);
                    }
                }
                uint32_t bf[4][2];
                #pragma unroll
                for (int ni = 0; ni < 4; ni++) {
                    const char* bp = Bp + boff1 + ni * 8 * AROW + k * 32;
                    bf[ni][0] = lds32(bp);
                    bf[ni][1] = lds32(bp + 16);
                }
                #pragma unroll
                for (int mi = 0; mi < 2; mi++)
                    if (mi < MMAX)
                        #pragma unroll
                        for (int ni = 0; ni < 4; ni++)
                            mma_tf32(acc[mi][ni], af[mi], bf[ni]);
            }
        }
        barh(hid);     // K reads done before H0 overwrite

        // ---- epilogue1: +c, PReLU(a0), tf32-round -> A half region ----
        #pragma unroll
        for (int mi = 0; mi < 2; mi++) {
            if (mi < MMAX) {
                #pragma unroll
                for (int ni = 0; ni < 4; ni++)
                    #pragma unroll
                    for (int rr = 0; rr < 2; rr++) {
                        const int row = rb + mi * 16 + rr * 8;
                        const int col = wn * 32 + ni * 8 + (lane & 3) * 2;
                        const float2 al = al0[(mi * 2 + rr) * 4 + ni];
                        float x0 = acc[mi][ni][rr * 2 + 0] + fC[col];
                        float x1 = acc[mi][ni][rr * 2 + 1] + fC[col + 1];
                        if (x0 < 0.f) x0 *= al.x;
                        if (x1 < 0.f) x1 *= al.y;
                        uint2 u; u.x = tf32r(x0); u.y = tf32r(x1);
                        *(uint2*)(Ah + row * AROW + col * 4) = u;
                    }
            }
        }

        // ---- prefetch epi2 alphas (hide under GEMM2) ----
        float2 al1[8];
        if (MMAX > 0) {
            #pragma unroll
            for (int mi = 0; mi < 2; mi++)
                #pragma unroll
                for (int rr = 0; rr < 2; rr++)
                    #pragma unroll
                    for (int ni = 0; ni < 2; ni++) {
                        int t = tbase + rb + mi * 16 + rr * 8;
                        int tc = t < 200 ? t : 199;
                        int g = wn * 16 + ni * 8 + (lane & 3) * 2;
                        al1[(mi * 2 + rr) * 2 + ni] =
                            __ldg((const float2*)&a1[tc * 64 + g]);
                    }
        }
        barh(hid);

        // ---- GEMM2: 32x16 warp tile ----
        float acc2[2][2][4];
        #pragma unroll
        for (int mi = 0; mi < 2; mi++)
            #pragma unroll
            for (int ni = 0; ni < 2; ni++)
                #pragma unroll
                for (int q = 0; q < 4; q++) acc2[mi][ni][q] = 0.f;
        if (MMAX > 0) {
            const char* Bp = smb + SMB_W1 + wn * 16 * AROW;
            #pragma unroll 4
            for (int k = 0; k < 16; k++) {
                uint32_t af[2][4];
                #pragma unroll
                for (int mi = 0; mi < 2; mi++) {
                    if (mi < MMAX) {
                        const char* ap = Ah + aoff + mi * 16 * AROW + k * 32;
                        af[mi][0] = lds32(ap);
                        af[mi][1] = lds32(ap + 8 * AROW);
                        af[mi][2] = lds32(ap + 16);
                        af[mi][3] = lds32(ap + 8 * AROW + 16);
                    }
                }
                uint32_t bf[2][2];
                #pragma unroll
                for (int ni = 0; ni < 2; ni++) {
                    const char* bp = Bp + boff1 + ni * 8 * AROW + k * 32;
                    bf[ni][0] = lds32(bp);
                    bf[ni][1] = lds32(bp + 16);
                }
                #pragma unroll
                for (int mi = 0; mi < 2; mi++)
                    if (mi < MMAX)
                        #pragma unroll
                        for (int ni = 0; ni < 2; ni++)
                            mma_tf32(acc2[mi][ni], af[mi], bf[ni]);
            }
        }

        // ---- epilogue2: +b1, PReLU(a1), dot Wout -> per-wn partials ----
        {
            float racc[4] = {0.f, 0.f, 0.f, 0.f};
            if (MMAX > 0) {
                #pragma unroll
                for (int mi = 0; mi < 2; mi++)
                    if (mi < MMAX)
                        #pragma unroll
                        for (int ni = 0; ni < 2; ni++)
                            #pragma unroll
                            for (int rr = 0; rr < 2; rr++) {
                                const int g = wn * 16 + ni * 8 + (lane & 3) * 2;
                                const float2 al = al1[(mi * 2 + rr) * 2 + ni];
                                float x0 = acc2[mi][ni][rr * 2 + 0] + fB1[g];
                                float x1 = acc2[mi][ni][rr * 2 + 1] + fB1[g + 1];
                                if (x0 < 0.f) x0 *= al.x;
                                if (x1 < 0.f) x1 *= al.y;
                                racc[mi * 2 + rr] += x0 * fWO[g] + x1 * fWO[g + 1];
                            }
            }
            #pragma unroll
            for (int i = 0; i < 4; i++) {
                racc[i] += __shfl_xor_sync(0xffffffffu, racc[i], 1);
                racc[i] += __shfl_xor_sync(0xffffffffu, racc[i], 2);
            }
            if ((lane & 3) == 0) {
                #pragma unroll
                for (int i = 0; i < 4; i++) {
                    const int row = rb + (i >> 1) * 16 + (i & 1) * 8;
                    fP[wn * 128 + hid * 64 + row] = racc[i];
                }
            }
            barh(hid);
            if (htid < 64) {
                const int row = htid;
                const int t = tbase + row;
                if (t < 200) {
                    const int ix = hid * 64 + row;
                    float lg = ((fP[ix] + fP[128 + ix]) + (fP[256 + ix] + fP[384 + ix]))
                               + boutv;
                    if (iMSK[t] == 0) lg = MASK_PAD;
                    fLOG[t] = lg;
                }
            }
            barh(hid);   // fP reads done before next tile's partial writes
        }
    }

    __syncthreads();

    // ---- softmax over 200 logits (16 warps) ----
    float v = (tid < 200) ? fLOG[tid] : -3.4e38f;
    float m = v;
    #pragma unroll
    for (int o = 16; o > 0; o >>= 1)
        m = fmaxf(m, __shfl_xor_sync(0xffffffffu, m, o));
    if (lane == 0) fRED[wid] = m;
    __syncthreads();
    float mx = fRED[0];
    #pragma unroll
    for (int i = 1; i < 16; i++) mx = fmaxf(mx, fRED[i]);
    float e = (tid < 200) ? __expf(v - mx) : 0.f;
    float s = e;
    #pragma unroll
    for (int o = 16; o > 0; o >>= 1)
        s += __shfl_xor_sync(0xffffffffu, s, o);
    __syncthreads();
    if (lane == 0) fRED[wid] = s;
    __syncthreads();
    float tot = 0.f;
    #pragma unroll
    for (int i = 0; i < 16; i++) tot += fRED[i];
    if (tid < 200) fLOG[tid] = e / tot;
    __syncthreads();

    // ---- out[b,:] = attn @ V  (4-way split over t) ----
    float* scr = (float*)(smb + SMB_A);
    const int quarter = tid >> 7;        // 0..3 -> t chunks of 50
    const int dch = tid & 127;
    const float* vb = val + ((size_t)b * 200 + quarter * 50) * 128 + dch;
    const float* at = &fLOG[quarter * 50];
    float s0 = 0.f, s1 = 0.f;
    #pragma unroll 5
    for (int t = 0; t < 50; t += 2) {
        s0 += at[t + 0] * vb[(size_t)(t + 0) * 128];
        s1 += at[t + 1] * vb[(size_t)(t + 1) * 128];
    }
    scr[tid] = s0 + s1;
    __syncthreads();
    if (tid < 128)
        out[(size_t)b * 128 + tid] =
            (scr[tid] + scr[tid + 128]) + (scr[tid + 256] + scr[tid + 384]);
}

extern "C" void kernel_launch(void* const* d_in, const int* in_sizes, int n_in,
                              void* d_out, int out_size) {
    (void)in_sizes; (void)n_in; (void)out_size;
    const float* query = (const float*)d_in[0];
    const float* key   = (const float*)d_in[1];
    const float* val   = (const float*)d_in[2];
    const int*   mask  = (const int*)d_in[3];
    const float* W0    = (const float*)d_in[4];
    const float* b0    = (const float*)d_in[5];
    const float* a0    = (const float*)d_in[6];
    const float* W1    = (const float*)d_in[7];
    const float* b1    = (const float*)d_in[8];
    const float* a1    = (const float*)d_in[9];
    const float* Wout  = (const float*)d_in[10];
    const float* bout  = (const float*)d_in[11];
    float* out = (float*)d_out;

    cudaFuncSetAttribute(din7_kernel, cudaFuncAttributeMaxDynamicSharedMemorySize,
                         SMB_TOT);
    prep_kernel<<<64, 256>>>(W0);
    din7_kernel<<<2048, NTHR, SMB_TOT>>>(query, key, val, mask, W0, b0, a0,
                                         W1, b1, a1, Wout, bout, out);
}